// round 2
// baseline (speedup 1.0000x reference)
#include <cuda_runtime.h>
#include <cstddef>

#define NB     8
#define DIMC   64
#define TLEN   16384
#define INNER  128

// ---------------- device scratch (no allocations allowed) ----------------
__device__ float g_eq[(size_t)NB * INNER * TLEN];   // exp(q), 64 MiB
__device__ float g_sq  [NB * INNER];                // sum_t exp(q)
__device__ float g_ksum[NB * INNER];                // sum_t softmax_d(k)
__device__ float g_vsum[NB * INNER];                // sum_t v
__device__ float g_A   [NB * 64 * INNER];           // w_out * ksum*vsum/sq

typedef unsigned long long u64;

__device__ __forceinline__ u64 bcast2(float a) {
    u64 r; asm("mov.b64 %0, {%1, %1};" : "=l"(r) : "f"(a)); return r;
}
__device__ __forceinline__ u64 fma2(u64 a, u64 b, u64 c) {
    u64 d; asm("fma.rn.f32x2 %0, %1, %2, %3;" : "=l"(d) : "l"(a), "l"(b), "l"(c)); return d;
}
__device__ __forceinline__ float2 unp2(u64 v) {
    float lo, hi; asm("mov.b64 {%0, %1}, %2;" : "=f"(lo), "=f"(hi) : "l"(v));
    return make_float2(lo, hi);
}

// ---------------- K0: zero stat accumulators ----------------
extern "C" __global__ void k_zero() {
    int i = blockIdx.x * 256 + threadIdx.x;
    if (i < NB * INNER) { g_sq[i] = 0.f; g_ksum[i] = 0.f; g_vsum[i] = 0.f; }
}

// ---------------- K1: QKV GEMM + exp + stats ----------------
// grid (TLEN/128, 3 groups, NB), block 256
// group 0 = q rows 0..127, group 1 = k rows 128..255, group 2 = v rows 256..383
extern "C" __global__ void __launch_bounds__(256, 2)
k_qkv(const float* __restrict__ x, const float* __restrict__ w) {
    extern __shared__ float sm[];
    float* ws    = sm;          // [64][128]  W transposed: ws[kk*128 + c]
    float* xs    = sm + 8192;   // [64][128]  x tile:       xs[kk*128 + t]
    float* stats = sm + 8192;   // aliased after compute

    const int tid = threadIdx.x;
    const int g  = blockIdx.y;
    const int b  = blockIdx.z;
    const int t0 = blockIdx.x * 128;

    // W (transposed into smem; strided gmem reads are L2-resident after wave 1)
    const float* wg = w + g * INNER * DIMC;
    #pragma unroll
    for (int i = 0; i < 8192; i += 256) {
        int idx = i + tid;
        int kk = idx >> 7, c = idx & 127;
        ws[idx] = wg[c * DIMC + kk];
    }
    // x tile (naturally [dim][t], coalesced float4)
    const float* xb = x + ((size_t)b * DIMC) * TLEN + t0;
    #pragma unroll
    for (int i = 0; i < 2048; i += 256) {
        int idx = i + tid;
        int kk = idx >> 5, t4 = idx & 31;
        ((float4*)xs)[idx] = *(const float4*)&xb[(size_t)kk * TLEN + t4 * 4];
    }
    __syncthreads();

    const int tx = tid & 15, ty = tid >> 4;
    const int cb = ty * 8;     // 8 channels per thread
    const int tb = tx * 8;     // 8 timesteps per thread (4 f32x2 pairs)

    u64 acc[8][4];
    #pragma unroll
    for (int i = 0; i < 8; i++)
        #pragma unroll
        for (int j = 0; j < 4; j++) acc[i][j] = 0ull;

    #pragma unroll 4
    for (int kk = 0; kk < 64; kk++) {
        ulonglong2 p0 = *(const ulonglong2*)&xs[kk * 128 + tb];
        ulonglong2 p1 = *(const ulonglong2*)&xs[kk * 128 + tb + 4];
        u64 xv[4] = { p0.x, p0.y, p1.x, p1.y };
        float4 w0 = *(const float4*)&ws[kk * 128 + cb];
        float4 w1 = *(const float4*)&ws[kk * 128 + cb + 4];
        float wv[8] = { w0.x, w0.y, w0.z, w0.w, w1.x, w1.y, w1.z, w1.w };
        #pragma unroll
        for (int i = 0; i < 8; i++) {
            u64 wb = bcast2(wv[i]);
            #pragma unroll
            for (int j = 0; j < 4; j++) acc[i][j] = fma2(wb, xv[j], acc[i][j]);
        }
    }
    __syncthreads();   // done with ws/xs; stats region may be reused

    float vv[8][8];
    #pragma unroll
    for (int i = 0; i < 8; i++)
        #pragma unroll
        for (int j = 0; j < 4; j++) {
            float2 f = unp2(acc[i][j]);
            vv[i][2 * j] = f.x; vv[i][2 * j + 1] = f.y;
        }

    if (g == 0) {
        // q: exp, store eq, accumulate sum_t exp(q)
        float* kpart = stats;  // [128][17]
        #pragma unroll
        for (int i = 0; i < 8; i++) {
            float s = 0.f;
            #pragma unroll
            for (int j = 0; j < 8; j++) { vv[i][j] = __expf(vv[i][j]); s += vv[i][j]; }
            size_t base = ((size_t)(b * INNER + cb + i)) * TLEN + t0 + tb;
            *(float4*)&g_eq[base]     = make_float4(vv[i][0], vv[i][1], vv[i][2], vv[i][3]);
            *(float4*)&g_eq[base + 4] = make_float4(vv[i][4], vv[i][5], vv[i][6], vv[i][7]);
            kpart[(cb + i) * 17 + tx] = s;
        }
        __syncthreads();
        if (tid < 128) {
            float s = 0.f;
            #pragma unroll
            for (int xk = 0; xk < 16; xk++) s += kpart[tid * 17 + xk];
            atomicAdd(&g_sq[b * INNER + tid], s);
        }
    } else if (g == 2) {
        // v: accumulate sum_t v
        float* kpart = stats;
        #pragma unroll
        for (int i = 0; i < 8; i++) {
            float s = 0.f;
            #pragma unroll
            for (int j = 0; j < 8; j++) s += vv[i][j];
            kpart[(cb + i) * 17 + tx] = s;
        }
        __syncthreads();
        if (tid < 128) {
            float s = 0.f;
            #pragma unroll
            for (int xk = 0; xk < 16; xk++) s += kpart[tid * 17 + xk];
            atomicAdd(&g_vsum[b * INNER + tid], s);
        }
    } else {
        // k: softmax over head-dim (32 channels per head), then sum over t
        float* pden  = stats;          // [16][128]
        float* rden  = stats + 2048;   // [4][128]
        float* kpart = stats + 2560;   // [128][17]
        float pd[8];
        #pragma unroll
        for (int j = 0; j < 8; j++) pd[j] = 0.f;
        #pragma unroll
        for (int i = 0; i < 8; i++)
            #pragma unroll
            for (int j = 0; j < 8; j++) { vv[i][j] = __expf(vv[i][j]); pd[j] += vv[i][j]; }
        #pragma unroll
        for (int j = 0; j < 8; j++) pden[ty * 128 + tb + j] = pd[j];
        __syncthreads();
        for (int idx = tid; idx < 512; idx += 256) {
            int h = idx >> 7, t = idx & 127;
            float d = pden[(4 * h + 0) * 128 + t] + pden[(4 * h + 1) * 128 + t]
                    + pden[(4 * h + 2) * 128 + t] + pden[(4 * h + 3) * 128 + t];
            rden[h * 128 + t] = 1.0f / d;
        }
        __syncthreads();
        const int h = cb >> 5;
        #pragma unroll
        for (int i = 0; i < 8; i++) {
            float s = 0.f;
            #pragma unroll
            for (int j = 0; j < 8; j++) s += vv[i][j] * rden[h * 128 + tb + j];
            kpart[(cb + i) * 17 + tx] = s;
        }
        __syncthreads();
        if (tid < 128) {
            float s = 0.f;
            #pragma unroll
            for (int xk = 0; xk < 16; xk++) s += kpart[tid * 17 + xk];
            atomicAdd(&g_ksum[b * INNER + tid], s);
        }
    }
}

// ---------------- K2: A[b][o][c] = w_out[o][c]*ksum*vsum/sq ----------------
extern "C" __global__ void k_prepA(const float* __restrict__ w_out) {
    int b = blockIdx.x;
    for (int idx = threadIdx.x; idx < 64 * INNER; idx += 256) {
        int o = idx >> 7, c = idx & 127;
        float s = g_ksum[b * INNER + c] * g_vsum[b * INNER + c] / g_sq[b * INNER + c];
        g_A[(b * 64 + o) * INNER + c] = w_out[o * INNER + c] * s;
    }
}

// ---------------- K3: y = A @ eq + b_out ----------------
// grid (TLEN/256, NB), block 256; tile 64 o x 256 t, K=128 in 2 chunks of 64
extern "C" __global__ void __launch_bounds__(256, 2)
k_out(const float* __restrict__ bo, float* __restrict__ y) {
    extern __shared__ float sm[];
    float* As = sm;          // [64][128]
    float* es = sm + 8192;   // [64][256] chunk

    const int tid = threadIdx.x;
    const int b = blockIdx.y;
    const int t0 = blockIdx.x * 256;

    #pragma unroll
    for (int i = 0; i < 2048; i += 256)
        ((float4*)As)[i + tid] = ((const float4*)(g_A + b * 64 * INNER))[i + tid];

    const int tx = tid & 31, ty = tid >> 5;
    const int ob = ty * 8;   // 8 out channels
    const int tb = tx * 8;   // 8 timesteps (4 pairs)

    u64 acc[8][4];
    #pragma unroll
    for (int i = 0; i < 8; i++)
        #pragma unroll
        for (int j = 0; j < 4; j++) acc[i][j] = 0ull;

    for (int ch = 0; ch < 2; ch++) {
        __syncthreads();
        const float* ep = g_eq + ((size_t)(b * INNER + ch * 64)) * TLEN + t0;
        #pragma unroll
        for (int i = 0; i < 4096; i += 256) {
            int idx = i + tid;
            int cc = idx >> 6, t4 = idx & 63;
            *(float4*)&es[cc * 256 + t4 * 4] = *(const float4*)&ep[(size_t)cc * TLEN + t4 * 4];
        }
        __syncthreads();
        #pragma unroll 2
        for (int c4 = 0; c4 < 16; c4++) {
            float4 av[8];
            #pragma unroll
            for (int i = 0; i < 8; i++)
                av[i] = *(const float4*)&As[(ob + i) * 128 + ch * 64 + c4 * 4];
            #pragma unroll
            for (int u = 0; u < 4; u++) {
                int c = c4 * 4 + u;
                ulonglong2 p0 = *(const ulonglong2*)&es[c * 256 + tb];
                ulonglong2 p1 = *(const ulonglong2*)&es[c * 256 + tb + 4];
                u64 xv[4] = { p0.x, p0.y, p1.x, p1.y };
                #pragma unroll
                for (int i = 0; i < 8; i++) {
                    u64 ab = bcast2(((const float*)&av[i])[u]);
                    #pragma unroll
                    for (int j = 0; j < 4; j++) acc[i][j] = fma2(ab, xv[j], acc[i][j]);
                }
            }
        }
    }

    #pragma unroll
    for (int i = 0; i < 8; i++) {
        float bias = __ldg(&bo[ob + i]);
        float2 f0 = unp2(acc[i][0]), f1 = unp2(acc[i][1]);
        float2 f2 = unp2(acc[i][2]), f3 = unp2(acc[i][3]);
        size_t base = ((size_t)(b * 64 + ob + i)) * TLEN + t0 + tb;
        *(float4*)&y[base]     = make_float4(f0.x + bias, f0.y + bias, f1.x + bias, f1.y + bias);
        *(float4*)&y[base + 4] = make_float4(f2.x + bias, f2.y + bias, f3.x + bias, f3.y + bias);
    }
}

// ---------------- launch ----------------
extern "C" void kernel_launch(void* const* d_in, const int* in_sizes, int n_in,
                              void* d_out, int out_size) {
    const float* x     = (const float*)d_in[0];
    const float* w_qkv = (const float*)d_in[1];
    const float* w_out = (const float*)d_in[2];
    const float* b_out = (const float*)d_in[3];
    float* y = (float*)d_out;

    cudaFuncSetAttribute(k_qkv, cudaFuncAttributeMaxDynamicSharedMemorySize, 65536);
    cudaFuncSetAttribute(k_out, cudaFuncAttributeMaxDynamicSharedMemorySize, 98304);

    k_zero<<<4, 256>>>();
    k_qkv<<<dim3(TLEN / 128, 3, NB), 256, 65536>>>(x, w_qkv);
    k_prepA<<<NB, 256>>>(w_out);
    k_out<<<dim3(TLEN / 256, NB), 256, 98304>>>(b_out, y);
}

// round 3
// speedup vs baseline: 1.2193x; 1.2193x over previous
#include <cuda_runtime.h>
#include <cstddef>

#define NB     8
#define DIMC   64
#define TLEN   16384
#define INNER  128

typedef unsigned long long u64;

// ---------------- device scratch (no allocations allowed) ----------------
__device__ float g_eq[(size_t)NB * INNER * TLEN];          // exp(q), 64 MiB
__device__ float g_sq  [NB * INNER];                       // sum_t exp(q)
__device__ float g_ksum[NB * INNER];                       // sum_t softmax_d(k)
__device__ float g_xsum[NB * DIMC];                        // sum_t x  (for vsum)
__device__ __align__(16) u64 g_A2[(size_t)NB * INNER * 64]; // A dup-pairs, [b][c][o]

__device__ __forceinline__ u64 bcast2(float a) {
    u64 r; asm("mov.b64 %0, {%1, %1};" : "=l"(r) : "f"(a)); return r;
}
__device__ __forceinline__ u64 fma2(u64 a, u64 b, u64 c) {
    u64 d; asm("fma.rn.f32x2 %0, %1, %2, %3;" : "=l"(d) : "l"(a), "l"(b), "l"(c)); return d;
}
__device__ __forceinline__ float2 unp2(u64 v) {
    float lo, hi; asm("mov.b64 {%0, %1}, %2;" : "=f"(lo), "=f"(hi) : "l"(v));
    return make_float2(lo, hi);
}

// ---------------- K0: zero stat accumulators ----------------
extern "C" __global__ void k_zero() {
    int i = blockIdx.x * 256 + threadIdx.x;
    if (i < NB * INNER) { g_sq[i] = 0.f; g_ksum[i] = 0.f; }
    if (i < NB * DIMC)  g_xsum[i] = 0.f;
}

// ---------------- K1: Q/K GEMM + exp + stats (+ x time-sum) ----------------
// grid (TLEN/128, 2 groups, NB), block 256
// group 0 = q rows 0..127 (also accumulates sum_t x), group 1 = k rows 128..255
extern "C" __global__ void __launch_bounds__(256, 2)
k_qkv(const float* __restrict__ x, const float* __restrict__ w) {
    extern __shared__ float sm[];
    u64*   ws2   = (u64*)sm;        // [64][128] dup W, 64 KB
    float* xs    = sm + 16384;      // [64][128] x tile, 32 KB
    float* stats = sm;              // alias over ws2 after mainloop

    const int tid = threadIdx.x;
    const int g  = blockIdx.y;
    const int b  = blockIdx.z;
    const int t0 = blockIdx.x * 128;

    // W tile, duplicated pairs (strided gmem reads; L2-resident after wave 1)
    const float* wg = w + g * (INNER * DIMC);
    #pragma unroll
    for (int i = 0; i < 8192; i += 256) {
        int idx = i + tid;
        int kk = idx >> 7, c = idx & 127;
        ws2[idx] = bcast2(wg[c * DIMC + kk]);
    }
    // x tile (naturally [dim][t], coalesced float4)
    const float* xb = x + ((size_t)b * DIMC) * TLEN + t0;
    #pragma unroll
    for (int i = 0; i < 2048; i += 256) {
        int idx = i + tid;
        int kk = idx >> 5, t4 = idx & 31;
        ((float4*)xs)[idx] = *(const float4*)&xb[(size_t)kk * TLEN + t4 * 4];
    }
    __syncthreads();

    const int tx = tid & 15, ty = tid >> 4;
    const int cb = ty * 8;     // 8 channels per thread
    const int ta = tx * 4;     // t quads: [ta, ta+3] and [64+ta, 64+ta+3]

    u64 acc[8][4];
    #pragma unroll
    for (int i = 0; i < 8; i++)
        #pragma unroll
        for (int j = 0; j < 4; j++) acc[i][j] = 0ull;

    #pragma unroll 4
    for (int kk = 0; kk < 64; kk++) {
        const float* xr = &xs[kk * 128];
        ulonglong2 a0 = *(const ulonglong2*)&xr[ta];
        ulonglong2 a1 = *(const ulonglong2*)&xr[64 + ta];
        u64 xv[4] = { a0.x, a0.y, a1.x, a1.y };
        const u64* wr = &ws2[kk * 128 + cb];
        ulonglong2 w01 = *(const ulonglong2*)&wr[0];
        ulonglong2 w23 = *(const ulonglong2*)&wr[2];
        ulonglong2 w45 = *(const ulonglong2*)&wr[4];
        ulonglong2 w67 = *(const ulonglong2*)&wr[6];
        u64 wv[8] = { w01.x, w01.y, w23.x, w23.y, w45.x, w45.y, w67.x, w67.y };
        #pragma unroll
        for (int i = 0; i < 8; i++)
            #pragma unroll
            for (int j = 0; j < 4; j++) acc[i][j] = fma2(wv[i], xv[j], acc[i][j]);
    }
    __syncthreads();   // done with ws2; stats region (aliased) now writable

    // unpack: vv[i][0..3] = t=ta+j, vv[i][4..7] = t=64+ta+j
    float vv[8][8];
    #pragma unroll
    for (int i = 0; i < 8; i++)
        #pragma unroll
        for (int j = 0; j < 4; j++) {
            float2 f = unp2(acc[i][j]);
            vv[i][2 * j] = f.x; vv[i][2 * j + 1] = f.y;
        }
    // NB: acc[i] = {quadA pair0, quadA pair1, quadB pair0, quadB pair1}
    // so vv[i][0..3] = quadA, vv[i][4..7] = quadB. (2*j mapping above interleaves
    // correctly since j=0,1 are quadA pairs and j=2,3 quadB pairs.)

    if (g == 0) {
        // ---- q: exp, store eq, accumulate sum_t exp(q); also sum_t x ----
        float* kpart = stats;  // [128][17]
        #pragma unroll
        for (int i = 0; i < 8; i++) {
            float s = 0.f;
            #pragma unroll
            for (int j = 0; j < 8; j++) { vv[i][j] = __expf(vv[i][j]); s += vv[i][j]; }
            size_t base = ((size_t)(b * INNER + cb + i)) * TLEN + t0;
            *(float4*)&g_eq[base + ta]      = make_float4(vv[i][0], vv[i][1], vv[i][2], vv[i][3]);
            *(float4*)&g_eq[base + 64 + ta] = make_float4(vv[i][4], vv[i][5], vv[i][6], vv[i][7]);
            kpart[(cb + i) * 17 + tx] = s;
        }
        // sum_t x from the (still valid) xs tile: thread -> (row, rotated seg)
        {
            int row = tid >> 2, seg = ((tid & 3) + row) & 3;
            const float* xr = &xs[row * 128 + seg * 32];
            float s = 0.f;
            #pragma unroll
            for (int q4 = 0; q4 < 8; q4++) {
                float4 v4 = *(const float4*)&xr[q4 * 4];
                s += v4.x + v4.y + v4.z + v4.w;
            }
            s += __shfl_down_sync(0xffffffffu, s, 1, 4);
            s += __shfl_down_sync(0xffffffffu, s, 2, 4);
            if ((tid & 3) == 0) atomicAdd(&g_xsum[b * DIMC + row], s);
        }
        __syncthreads();
        if (tid < 128) {
            float s = 0.f;
            #pragma unroll
            for (int xk = 0; xk < 16; xk++) s += kpart[tid * 17 + xk];
            atomicAdd(&g_sq[b * INNER + tid], s);
        }
    } else {
        // ---- k: softmax over head-dim (32 ch per head), then sum over t ----
        float* pden  = stats;          // [16][128]
        float* rden  = stats + 2048;   // [4][128]
        float* kpart = stats + 2560;   // [128][17]
        float pd[8];
        #pragma unroll
        for (int j = 0; j < 8; j++) pd[j] = 0.f;
        #pragma unroll
        for (int i = 0; i < 8; i++)
            #pragma unroll
            for (int j = 0; j < 8; j++) { vv[i][j] = __expf(vv[i][j]); pd[j] += vv[i][j]; }
        *(float4*)&pden[ty * 128 + ta]      = make_float4(pd[0], pd[1], pd[2], pd[3]);
        *(float4*)&pden[ty * 128 + 64 + ta] = make_float4(pd[4], pd[5], pd[6], pd[7]);
        __syncthreads();
        for (int idx = tid; idx < 512; idx += 256) {
            int h = idx >> 7, t = idx & 127;
            float d = pden[(4 * h + 0) * 128 + t] + pden[(4 * h + 1) * 128 + t]
                    + pden[(4 * h + 2) * 128 + t] + pden[(4 * h + 3) * 128 + t];
            rden[h * 128 + t] = 1.0f / d;
        }
        __syncthreads();
        const int h = ty >> 2;
        float4 r0 = *(const float4*)&rden[h * 128 + ta];
        float4 r1 = *(const float4*)&rden[h * 128 + 64 + ta];
        float rr[8] = { r0.x, r0.y, r0.z, r0.w, r1.x, r1.y, r1.z, r1.w };
        #pragma unroll
        for (int i = 0; i < 8; i++) {
            float s = 0.f;
            #pragma unroll
            for (int j = 0; j < 8; j++) s += vv[i][j] * rr[j];
            kpart[(cb + i) * 17 + tx] = s;
        }
        __syncthreads();
        if (tid < 128) {
            float s = 0.f;
            #pragma unroll
            for (int xk = 0; xk < 16; xk++) s += kpart[tid * 17 + xk];
            atomicAdd(&g_ksum[b * INNER + tid], s);
        }
    }
}

// ---------------- K2: vsum = W_v @ xsum;  A2[b][c][o] = dup(w_out[o][c]*scale[c]) --
extern "C" __global__ void k_prepA(const float* __restrict__ w,
                                   const float* __restrict__ w_out) {
    __shared__ float sc[INNER];
    const int b = blockIdx.x;
    const int tid = threadIdx.x;
    if (tid < INNER) {
        const float* wv = w + 2 * INNER * DIMC + tid * DIMC;  // W_v row
        float s = 0.f;
        #pragma unroll
        for (int k = 0; k < DIMC; k++) s += wv[k] * g_xsum[b * DIMC + k];
        sc[tid] = g_ksum[b * INNER + tid] * s / g_sq[b * INNER + tid];
    }
    __syncthreads();
    for (int idx = tid; idx < INNER * 64; idx += 256) {
        int c = idx >> 6, o = idx & 63;
        g_A2[((size_t)b * INNER + c) * 64 + o] = bcast2(w_out[o * INNER + c] * sc[c]);
    }
}

// ---------------- K3: y = A @ eq + b_out ----------------
// grid (TLEN/256, NB), block 256; tile 64 o x 256 t, K=128 in 4 chunks of 32
extern "C" __global__ void __launch_bounds__(256, 2)
k_out(const float* __restrict__ bo, float* __restrict__ y) {
    extern __shared__ float sm[];
    u64*   As2 = (u64*)sm;        // [128][64] dup A (transposed), 64 KB
    float* es  = sm + 16384;      // [32][256] eq chunk, 32 KB

    const int tid = threadIdx.x;
    const int b = blockIdx.y;
    const int t0 = blockIdx.x * 256;

    const ulonglong2* Ag = (const ulonglong2*)(g_A2 + (size_t)b * INNER * 64);
    #pragma unroll
    for (int i = 0; i < 4096; i += 256)
        ((ulonglong2*)As2)[i + tid] = Ag[i + tid];

    const int tx = tid & 31, ty = tid >> 5;
    const int ob = ty * 8;     // 8 out channels
    const int ta = tx * 4;     // t quads: [ta] and [128+ta]

    u64 acc[8][4];
    #pragma unroll
    for (int i = 0; i < 8; i++)
        #pragma unroll
        for (int j = 0; j < 4; j++) acc[i][j] = 0ull;

    for (int ch = 0; ch < 4; ch++) {
        __syncthreads();
        const float* ep = g_eq + ((size_t)(b * INNER + ch * 32)) * TLEN + t0;
        #pragma unroll
        for (int i = 0; i < 2048; i += 256) {
            int idx = i + tid;
            int cc = idx >> 6, t4 = idx & 63;
            *(float4*)&es[cc * 256 + t4 * 4] = *(const float4*)&ep[(size_t)cc * TLEN + t4 * 4];
        }
        __syncthreads();
        #pragma unroll 4
        for (int ci = 0; ci < 32; ci++) {
            const u64* ar = &As2[(ch * 32 + ci) * 64 + ob];
            ulonglong2 a01 = *(const ulonglong2*)&ar[0];
            ulonglong2 a23 = *(const ulonglong2*)&ar[2];
            ulonglong2 a45 = *(const ulonglong2*)&ar[4];
            ulonglong2 a67 = *(const ulonglong2*)&ar[6];
            u64 av[8] = { a01.x, a01.y, a23.x, a23.y, a45.x, a45.y, a67.x, a67.y };
            const float* er = &es[ci * 256];
            ulonglong2 e0 = *(const ulonglong2*)&er[ta];
            ulonglong2 e1 = *(const ulonglong2*)&er[128 + ta];
            u64 xv[4] = { e0.x, e0.y, e1.x, e1.y };
            #pragma unroll
            for (int i = 0; i < 8; i++)
                #pragma unroll
                for (int j = 0; j < 4; j++) acc[i][j] = fma2(av[i], xv[j], acc[i][j]);
        }
    }

    #pragma unroll
    for (int i = 0; i < 8; i++) {
        float bias = __ldg(&bo[ob + i]);
        float2 f0 = unp2(acc[i][0]), f1 = unp2(acc[i][1]);
        float2 f2 = unp2(acc[i][2]), f3 = unp2(acc[i][3]);
        size_t base = ((size_t)(b * 64 + ob + i)) * TLEN + t0;
        *(float4*)&y[base + ta]       = make_float4(f0.x + bias, f0.y + bias, f1.x + bias, f1.y + bias);
        *(float4*)&y[base + 128 + ta] = make_float4(f2.x + bias, f2.y + bias, f3.x + bias, f3.y + bias);
    }
}

// ---------------- launch ----------------
extern "C" void kernel_launch(void* const* d_in, const int* in_sizes, int n_in,
                              void* d_out, int out_size) {
    const float* x     = (const float*)d_in[0];
    const float* w_qkv = (const float*)d_in[1];
    const float* w_out = (const float*)d_in[2];
    const float* b_out = (const float*)d_in[3];
    float* y = (float*)d_out;

    cudaFuncSetAttribute(k_qkv, cudaFuncAttributeMaxDynamicSharedMemorySize, 98304);
    cudaFuncSetAttribute(k_out, cudaFuncAttributeMaxDynamicSharedMemorySize, 98304);

    k_zero<<<4, 256>>>();
    k_qkv<<<dim3(TLEN / 128, 2, NB), 256, 98304>>>(x, w_qkv);
    k_prepA<<<NB, 256>>>(w_qkv, w_out);
    k_out<<<dim3(TLEN / 256, NB), 256, 98304>>>(b_out, y);
}

// round 4
// speedup vs baseline: 1.5549x; 1.2753x over previous
#include <cuda_runtime.h>
#include <cstddef>

#define NB     8
#define DIMC   64
#define TLEN   16384
#define INNER  128

typedef unsigned long long u64;

// ---------------- device scratch (no allocations allowed) ----------------
__device__ float g_eq[(size_t)NB * INNER * TLEN];          // exp(q), 64 MiB
__device__ float g_sq  [NB * INNER];                       // sum_t exp(q)
__device__ float g_ksum[NB * INNER];                       // sum_t softmax_d(k)
__device__ float g_xsum[NB * DIMC];                        // sum_t x  (for vsum)
__device__ __align__(16) u64 g_A2[(size_t)NB * INNER * 64]; // A dup-pairs, [b][c][o]
__device__ __align__(16) u64 g_W2[2 * 64 * 128];            // W dup-pairs, [g][kk][c]

__device__ __forceinline__ u64 bcast2(float a) {
    u64 r; asm("mov.b64 %0, {%1, %1};" : "=l"(r) : "f"(a)); return r;
}
__device__ __forceinline__ u64 fma2(u64 a, u64 b, u64 c) {
    u64 d; asm("fma.rn.f32x2 %0, %1, %2, %3;" : "=l"(d) : "l"(a), "l"(b), "l"(c)); return d;
}
__device__ __forceinline__ float2 unp2(u64 v) {
    float lo, hi; asm("mov.b64 {%0, %1}, %2;" : "=f"(lo), "=f"(hi) : "l"(v));
    return make_float2(lo, hi);
}
__device__ __forceinline__ void cpa16(void* s, const void* g) {
    unsigned sa = (unsigned)__cvta_generic_to_shared(s);
    asm volatile("cp.async.cg.shared.global [%0], [%1], 16;\n" :: "r"(sa), "l"(g));
}
__device__ __forceinline__ void cpa_commit() {
    asm volatile("cp.async.commit_group;\n" ::: "memory");
}

// ---------------- K0: zero stats + build duplicated/transposed W ----------------
// grid 16 x 256
extern "C" __global__ void k_init(const float* __restrict__ w) {
    int gid = blockIdx.x * 256 + threadIdx.x;          // 0..4095
    if (gid < NB * INNER) { g_sq[gid] = 0.f; g_ksum[gid] = 0.f; }
    if (gid < NB * DIMC)  g_xsum[gid] = 0.f;
    #pragma unroll
    for (int j = 0; j < 4; j++) {
        int idx = gid * 4 + j;                         // 0..16383
        int g = idx >> 13, r = idx & 8191;
        int kk = r >> 7, c = r & 127;
        g_W2[idx] = bcast2(w[g * (INNER * DIMC) + c * DIMC + kk]);
    }
}

// ---------------- K1: Q/K GEMM + exp + stats (+ x time-sum) ----------------
// grid (TLEN/128, 2 groups, NB), block 256
// group 0 = q rows 0..127 (also accumulates sum_t x), group 1 = k rows 128..255
extern "C" __global__ void __launch_bounds__(256, 2)
k_qkv(const float* __restrict__ x) {
    extern __shared__ float sm[];
    u64*   ws2   = (u64*)sm;        // [64][128] dup W, 64 KB
    float* xs    = sm + 16384;      // [64][128] x tile, 32 KB
    float* stats = sm;              // alias over ws2 after mainloop

    const int tid = threadIdx.x;
    const int g  = blockIdx.y;
    const int b  = blockIdx.z;
    const int t0 = blockIdx.x * 128;

    // W tile: coalesced copy of pre-duplicated pairs (L2-resident)
    const ulonglong2* wsrc = (const ulonglong2*)(g_W2 + g * 8192);
    #pragma unroll
    for (int i = 0; i < 4096; i += 256)
        ((ulonglong2*)ws2)[i + tid] = wsrc[i + tid];
    // x tile (naturally [dim][t], coalesced float4)
    const float* xb = x + ((size_t)b * DIMC) * TLEN + t0;
    #pragma unroll
    for (int i = 0; i < 2048; i += 256) {
        int idx = i + tid;
        int kk = idx >> 5, t4 = idx & 31;
        ((float4*)xs)[idx] = *(const float4*)&xb[(size_t)kk * TLEN + t4 * 4];
    }
    __syncthreads();

    const int tx = tid & 15, ty = tid >> 4;
    const int cb = ty * 8;     // 8 channels per thread
    const int ta = tx * 4;     // t quads: [ta, ta+3] and [64+ta, 64+ta+3]

    u64 acc[8][4];
    #pragma unroll
    for (int i = 0; i < 8; i++)
        #pragma unroll
        for (int j = 0; j < 4; j++) acc[i][j] = 0ull;

    #pragma unroll 4
    for (int kk = 0; kk < 64; kk++) {
        const float* xr = &xs[kk * 128];
        ulonglong2 a0 = *(const ulonglong2*)&xr[ta];
        ulonglong2 a1 = *(const ulonglong2*)&xr[64 + ta];
        u64 xv[4] = { a0.x, a0.y, a1.x, a1.y };
        const u64* wr = &ws2[kk * 128 + cb];
        ulonglong2 w01 = *(const ulonglong2*)&wr[0];
        ulonglong2 w23 = *(const ulonglong2*)&wr[2];
        ulonglong2 w45 = *(const ulonglong2*)&wr[4];
        ulonglong2 w67 = *(const ulonglong2*)&wr[6];
        u64 wv[8] = { w01.x, w01.y, w23.x, w23.y, w45.x, w45.y, w67.x, w67.y };
        #pragma unroll
        for (int i = 0; i < 8; i++)
            #pragma unroll
            for (int j = 0; j < 4; j++) acc[i][j] = fma2(wv[i], xv[j], acc[i][j]);
    }
    __syncthreads();   // done with ws2; stats region (aliased) now writable

    // unpack: vv[i][0..3] = t=ta+j, vv[i][4..7] = t=64+ta+j
    float vv[8][8];
    #pragma unroll
    for (int i = 0; i < 8; i++)
        #pragma unroll
        for (int j = 0; j < 4; j++) {
            float2 f = unp2(acc[i][j]);
            vv[i][2 * j] = f.x; vv[i][2 * j + 1] = f.y;
        }

    if (g == 0) {
        // ---- q: exp, store eq, accumulate sum_t exp(q); also sum_t x ----
        float* kpart = stats;  // [128][17]
        #pragma unroll
        for (int i = 0; i < 8; i++) {
            float s = 0.f;
            #pragma unroll
            for (int j = 0; j < 8; j++) { vv[i][j] = __expf(vv[i][j]); s += vv[i][j]; }
            size_t base = ((size_t)(b * INNER + cb + i)) * TLEN + t0;
            *(float4*)&g_eq[base + ta]      = make_float4(vv[i][0], vv[i][1], vv[i][2], vv[i][3]);
            *(float4*)&g_eq[base + 64 + ta] = make_float4(vv[i][4], vv[i][5], vv[i][6], vv[i][7]);
            kpart[(cb + i) * 17 + tx] = s;
        }
        // sum_t x from the (still valid) xs tile: thread -> (row, rotated seg)
        {
            int row = tid >> 2, seg = ((tid & 3) + row) & 3;
            const float* xr = &xs[row * 128 + seg * 32];
            float s = 0.f;
            #pragma unroll
            for (int q4 = 0; q4 < 8; q4++) {
                float4 v4 = *(const float4*)&xr[q4 * 4];
                s += v4.x + v4.y + v4.z + v4.w;
            }
            s += __shfl_down_sync(0xffffffffu, s, 1, 4);
            s += __shfl_down_sync(0xffffffffu, s, 2, 4);
            if ((tid & 3) == 0) atomicAdd(&g_xsum[b * DIMC + row], s);
        }
        __syncthreads();
        if (tid < 128) {
            float s = 0.f;
            #pragma unroll
            for (int xk = 0; xk < 16; xk++) s += kpart[tid * 17 + xk];
            atomicAdd(&g_sq[b * INNER + tid], s);
        }
    } else {
        // ---- k: softmax over head-dim (32 ch per head), then sum over t ----
        float* pden  = stats;          // [16][128]
        float* rden  = stats + 2048;   // [4][128]
        float* kpart = stats + 2560;   // [128][17]
        float pd[8];
        #pragma unroll
        for (int j = 0; j < 8; j++) pd[j] = 0.f;
        #pragma unroll
        for (int i = 0; i < 8; i++)
            #pragma unroll
            for (int j = 0; j < 8; j++) { vv[i][j] = __expf(vv[i][j]); pd[j] += vv[i][j]; }
        *(float4*)&pden[ty * 128 + ta]      = make_float4(pd[0], pd[1], pd[2], pd[3]);
        *(float4*)&pden[ty * 128 + 64 + ta] = make_float4(pd[4], pd[5], pd[6], pd[7]);
        __syncthreads();
        for (int idx = tid; idx < 512; idx += 256) {
            int h = idx >> 7, t = idx & 127;
            float d = pden[(4 * h + 0) * 128 + t] + pden[(4 * h + 1) * 128 + t]
                    + pden[(4 * h + 2) * 128 + t] + pden[(4 * h + 3) * 128 + t];
            rden[h * 128 + t] = 1.0f / d;
        }
        __syncthreads();
        const int h = ty >> 2;
        float4 r0 = *(const float4*)&rden[h * 128 + ta];
        float4 r1 = *(const float4*)&rden[h * 128 + 64 + ta];
        float rr[8] = { r0.x, r0.y, r0.z, r0.w, r1.x, r1.y, r1.z, r1.w };
        #pragma unroll
        for (int i = 0; i < 8; i++) {
            float s = 0.f;
            #pragma unroll
            for (int j = 0; j < 8; j++) s += vv[i][j] * rr[j];
            kpart[(cb + i) * 17 + tx] = s;
        }
        __syncthreads();
        if (tid < 128) {
            float s = 0.f;
            #pragma unroll
            for (int xk = 0; xk < 16; xk++) s += kpart[tid * 17 + xk];
            atomicAdd(&g_ksum[b * INNER + tid], s);
        }
    }
}

// ---------------- K2: vsum = W_v @ xsum;  A2[b][c][o] = dup(w_out[o][c]*scale[c]) --
extern "C" __global__ void k_prepA(const float* __restrict__ w,
                                   const float* __restrict__ w_out) {
    __shared__ float sc[INNER];
    const int b = blockIdx.x;
    const int tid = threadIdx.x;
    if (tid < INNER) {
        const float* wv = w + 2 * INNER * DIMC + tid * DIMC;  // W_v row
        float s = 0.f;
        #pragma unroll
        for (int k = 0; k < DIMC; k++) s += wv[k] * g_xsum[b * DIMC + k];
        sc[tid] = g_ksum[b * INNER + tid] * s / g_sq[b * INNER + tid];
    }
    __syncthreads();
    for (int idx = tid; idx < INNER * 64; idx += 256) {
        int c = idx >> 6, o = idx & 63;
        g_A2[((size_t)b * INNER + c) * 64 + o] = bcast2(w_out[o * INNER + c] * sc[c]);
    }
}

// ---------------- K3: y = A @ eq + b_out ----------------
// grid (TLEN/256, NB), block 256; tile 64 o x 256 t
// K=128 in 8 chunks of 16, cp.async double-buffered
#define CHUNK 16
extern "C" __global__ void __launch_bounds__(256, 2)
k_out(const float* __restrict__ bo, float* __restrict__ y) {
    extern __shared__ float sm[];
    u64*   As2 = (u64*)sm;        // [128][64] dup A (transposed), 64 KB
    float* es  = sm + 16384;      // [2][16][256] eq chunks, 32 KB

    const int tid = threadIdx.x;
    const int b = blockIdx.y;
    const int t0 = blockIdx.x * 256;

    const ulonglong2* Ag = (const ulonglong2*)(g_A2 + (size_t)b * INNER * 64);
    #pragma unroll
    for (int i = 0; i < 4096; i += 256)
        ((ulonglong2*)As2)[i + tid] = Ag[i + tid];

    const float* ep = g_eq + ((size_t)b * INNER) * TLEN + t0;
    const int lrow = tid >> 6;          // 0..3  (4 rows per pass, 4 passes)
    const int lt4  = (tid & 63) * 4;    // 0..252

    // prologue: chunk 0 -> buf 0
    {
        const float* src = ep + (size_t)lrow * TLEN + lt4;
        float* dst = es + lrow * 256 + lt4;
        #pragma unroll
        for (int r = 0; r < CHUNK; r += 4)
            cpa16(dst + r * 256, src + (size_t)r * TLEN);
        cpa_commit();
    }

    const int tx = tid & 31, ty = tid >> 5;
    const int ob = ty * 8;     // 8 out channels
    const int ta = tx * 4;     // t quads: [ta] and [128+ta]

    u64 acc[8][4];
    #pragma unroll
    for (int i = 0; i < 8; i++)
        #pragma unroll
        for (int j = 0; j < 4; j++) acc[i][j] = 0ull;

    for (int cc = 0; cc < 8; cc++) {
        if (cc + 1 < 8) {
            const float* src = ep + ((size_t)((cc + 1) * CHUNK + lrow)) * TLEN + lt4;
            float* dst = es + ((cc + 1) & 1) * 4096 + lrow * 256 + lt4;
            #pragma unroll
            for (int r = 0; r < CHUNK; r += 4)
                cpa16(dst + r * 256, src + (size_t)r * TLEN);
            cpa_commit();
            asm volatile("cp.async.wait_group 1;\n" ::: "memory");
        } else {
            asm volatile("cp.async.wait_group 0;\n" ::: "memory");
        }
        __syncthreads();

        const float* eb = es + (cc & 1) * 4096;
        #pragma unroll 4
        for (int ci = 0; ci < CHUNK; ci++) {
            const u64* ar = &As2[(cc * CHUNK + ci) * 64 + ob];
            ulonglong2 a01 = *(const ulonglong2*)&ar[0];
            ulonglong2 a23 = *(const ulonglong2*)&ar[2];
            ulonglong2 a45 = *(const ulonglong2*)&ar[4];
            ulonglong2 a67 = *(const ulonglong2*)&ar[6];
            u64 av[8] = { a01.x, a01.y, a23.x, a23.y, a45.x, a45.y, a67.x, a67.y };
            const float* er = &eb[ci * 256];
            ulonglong2 e0 = *(const ulonglong2*)&er[ta];
            ulonglong2 e1 = *(const ulonglong2*)&er[128 + ta];
            u64 xv[4] = { e0.x, e0.y, e1.x, e1.y };
            #pragma unroll
            for (int i = 0; i < 8; i++)
                #pragma unroll
                for (int j = 0; j < 4; j++) acc[i][j] = fma2(av[i], xv[j], acc[i][j]);
        }
        __syncthreads();
    }

    #pragma unroll
    for (int i = 0; i < 8; i++) {
        float bias = __ldg(&bo[ob + i]);
        float2 f0 = unp2(acc[i][0]), f1 = unp2(acc[i][1]);
        float2 f2 = unp2(acc[i][2]), f3 = unp2(acc[i][3]);
        size_t base = ((size_t)(b * 64 + ob + i)) * TLEN + t0;
        *(float4*)&y[base + ta]       = make_float4(f0.x + bias, f0.y + bias, f1.x + bias, f1.y + bias);
        *(float4*)&y[base + 128 + ta] = make_float4(f2.x + bias, f2.y + bias, f3.x + bias, f3.y + bias);
    }
}

// ---------------- launch ----------------
extern "C" void kernel_launch(void* const* d_in, const int* in_sizes, int n_in,
                              void* d_out, int out_size) {
    const float* x     = (const float*)d_in[0];
    const float* w_qkv = (const float*)d_in[1];
    const float* w_out = (const float*)d_in[2];
    const float* b_out = (const float*)d_in[3];
    float* y = (float*)d_out;

    cudaFuncSetAttribute(k_qkv, cudaFuncAttributeMaxDynamicSharedMemorySize, 98304);
    cudaFuncSetAttribute(k_out, cudaFuncAttributeMaxDynamicSharedMemorySize, 98304);

    k_init<<<16, 256>>>(w_qkv);
    k_qkv<<<dim3(TLEN / 128, 2, NB), 256, 98304>>>(x);
    k_prepA<<<NB, 256>>>(w_qkv, w_out);
    k_out<<<dim3(TLEN / 256, NB), 256, 98304>>>(b_out, y);
}